// round 9
// baseline (speedup 1.0000x reference)
#include <cuda_runtime.h>
#include <cuda_bf16.h>

// Problem: DotProductAttention_83476984365340
// softmax over singleton axis == 1.0 -> output = values.sum(axis=1).
// Pure HBM-bound column sum of values [32, 4096, 1024] f32 (512 MiB read).
//
// History: 256 CTAs (1.7/SM), 2MiB aligned stream per CTA is the grid optimum.
//   R5  (BATCH=16 burst):        78.9us ncu, 6.86 TB/s
//   R8  (PIPE=8 double-buffer):  77.7us ncu, 6.96 TB/s, DRAM 87.8%  <- best
// R9: deepen pipeline to PIPE=12 (12-24 loads in flight vs 8-16), smoothing
// DRAM queue occupancy. 512 rows = 42*12 + 8 tail (batched). ~116 regs, no spill.

#define B_DIM 32
#define T_DIM 4096
#define D_DIM 1024
#define CHUNKS_PER_B 8
#define T_PER_CHUNK (T_DIM / CHUNKS_PER_B)  // 512 rows = 2 MiB per CTA
#define THREADS 256                          // 256 threads * float4 = 1024 = D
#define PIPE 12                              // double-buffer depth
#define NGROUPS (T_PER_CHUNK / PIPE)         // 42 full groups
#define TAIL (T_PER_CHUNK - NGROUPS * PIPE)  // 8 tail rows

__global__ __launch_bounds__(THREADS, 2)
void values_colsum_kernel(const float* __restrict__ values, float* __restrict__ out)
{
    const int b  = blockIdx.y;                 // 0..31
    const int c  = blockIdx.x;                 // 0..7
    const int d4 = threadIdx.x;                // float4 lane within row (0..255)

    const float4* __restrict__ p =
        reinterpret_cast<const float4*>(values) +
        (size_t)b * T_DIM * (D_DIM / 4) +
        (size_t)c * T_PER_CHUNK * (D_DIM / 4) +
        d4;

    float4 acc0 = make_float4(0.f, 0.f, 0.f, 0.f);
    float4 acc1 = make_float4(0.f, 0.f, 0.f, 0.f);

    // Prologue: fill buffer A.
    float4 va[PIPE], vb[PIPE];
    #pragma unroll
    for (int k = 0; k < PIPE; ++k)
        va[k] = p[(size_t)k * (D_DIM / 4)];
    p += (size_t)PIPE * (D_DIM / 4);

    // Steady state: NGROUPS-1 iterations, each issues next group's loads
    // before consuming the current group.
    for (int it = 0; it < NGROUPS - 1; ++it) {
        float4* cur  = (it & 1) ? vb : va;
        float4* next = (it & 1) ? va : vb;

        #pragma unroll
        for (int k = 0; k < PIPE; ++k)
            next[k] = p[(size_t)k * (D_DIM / 4)];
        p += (size_t)PIPE * (D_DIM / 4);

        #pragma unroll
        for (int k = 0; k < PIPE; k += 2) {
            acc0.x += cur[k].x;   acc0.y += cur[k].y;
            acc0.z += cur[k].z;   acc0.w += cur[k].w;
            acc1.x += cur[k+1].x; acc1.y += cur[k+1].y;
            acc1.z += cur[k+1].z; acc1.w += cur[k+1].w;
        }
    }

    // Drain last full group, overlapping the batched tail loads.
    {
        float4* cur  = ((NGROUPS - 1) & 1) ? vb : va;
        float4* next = ((NGROUPS - 1) & 1) ? va : vb;

        #pragma unroll
        for (int k = 0; k < TAIL; ++k)
            next[k] = p[(size_t)k * (D_DIM / 4)];

        #pragma unroll
        for (int k = 0; k < PIPE; k += 2) {
            acc0.x += cur[k].x;   acc0.y += cur[k].y;
            acc0.z += cur[k].z;   acc0.w += cur[k].w;
            acc1.x += cur[k+1].x; acc1.y += cur[k+1].y;
            acc1.z += cur[k+1].z; acc1.w += cur[k+1].w;
        }

        #pragma unroll
        for (int k = 0; k < TAIL; k += 2) {
            acc0.x += next[k].x;   acc0.y += next[k].y;
            acc0.z += next[k].z;   acc0.w += next[k].w;
            acc1.x += next[k+1].x; acc1.y += next[k+1].y;
            acc1.z += next[k+1].z; acc1.w += next[k+1].w;
        }
    }

    acc0.x += acc1.x; acc0.y += acc1.y; acc0.z += acc1.z; acc0.w += acc1.w;

    float* o = out + (size_t)b * D_DIM + d4 * 4;
    atomicAdd(o + 0, acc0.x);
    atomicAdd(o + 1, acc0.y);
    atomicAdd(o + 2, acc0.z);
    atomicAdd(o + 3, acc0.w);
}

extern "C" void kernel_launch(void* const* d_in, const int* in_sizes, int n_in,
                              void* d_out, int out_size)
{
    // Input order per reference setup_inputs(): query, keys, values, W
    const float* values = (const float*)d_in[2];
    float* out = (float*)d_out;

    cudaMemsetAsync(out, 0, (size_t)out_size * sizeof(float));

    dim3 grid(CHUNKS_PER_B, B_DIM);
    values_colsum_kernel<<<grid, THREADS>>>(values, out);
}

// round 10
// speedup vs baseline: 1.0091x; 1.0091x over previous
#include <cuda_runtime.h>
#include <cuda_bf16.h>

// Problem: DotProductAttention_83476984365340
// softmax over singleton axis == 1.0 -> output = values.sum(axis=1).
// Pure HBM-bound column sum of values [32, 4096, 1024] f32 (512 MiB read).
//
// Final configuration (R8), all axes swept:
//   grid: 256 CTAs = 8 chunks x 32 batches (1.7/SM, 2MiB aligned stream/CTA)
//     [148: 6.39 | 256: 6.96 | 296: 6.67 | 512: 6.61 | 1024: 6.38 TB/s]
//   schedule: 8-deep software-pipelined double buffer (80 regs)
//     [burst-16: 6.86 | pipe-8: 6.96 | pipe-12: 6.77 TB/s (128-reg cap spill)]
//   caching: default (evict-first .cs regressed)
// Result: ncu 77.7us, 6.96 TB/s = 87.8% DRAM — at the HBM3e streaming wall.

#define B_DIM 32
#define T_DIM 4096
#define D_DIM 1024
#define CHUNKS_PER_B 8
#define T_PER_CHUNK (T_DIM / CHUNKS_PER_B)  // 512 rows = 2 MiB per CTA
#define THREADS 256                          // 256 threads * float4 = 1024 = D
#define PIPE 8                               // double-buffer depth

__global__ __launch_bounds__(THREADS, 2)
void values_colsum_kernel(const float* __restrict__ values, float* __restrict__ out)
{
    const int b  = blockIdx.y;                 // 0..31
    const int c  = blockIdx.x;                 // 0..7
    const int d4 = threadIdx.x;                // float4 lane within row (0..255)

    const float4* __restrict__ p =
        reinterpret_cast<const float4*>(values) +
        (size_t)b * T_DIM * (D_DIM / 4) +
        (size_t)c * T_PER_CHUNK * (D_DIM / 4) +
        d4;

    float4 acc0 = make_float4(0.f, 0.f, 0.f, 0.f);
    float4 acc1 = make_float4(0.f, 0.f, 0.f, 0.f);

    // Prologue: fill buffer A.
    float4 va[PIPE], vb[PIPE];
    #pragma unroll
    for (int k = 0; k < PIPE; ++k)
        va[k] = p[(size_t)k * (D_DIM / 4)];
    p += (size_t)PIPE * (D_DIM / 4);

    // Steady state: 512 rows = 64 groups of 8; prologue loaded 1 group,
    // loop runs 63 iterations alternating buffers, epilogue drains the last.
    const int ITERS = T_PER_CHUNK / PIPE - 1;  // 63

    for (int it = 0; it < ITERS; ++it) {
        float4* cur  = (it & 1) ? vb : va;
        float4* next = (it & 1) ? va : vb;

        // Issue next group's loads BEFORE consuming current group.
        #pragma unroll
        for (int k = 0; k < PIPE; ++k)
            next[k] = p[(size_t)k * (D_DIM / 4)];
        p += (size_t)PIPE * (D_DIM / 4);

        #pragma unroll
        for (int k = 0; k < PIPE; k += 2) {
            acc0.x += cur[k].x;   acc0.y += cur[k].y;
            acc0.z += cur[k].z;   acc0.w += cur[k].w;
            acc1.x += cur[k+1].x; acc1.y += cur[k+1].y;
            acc1.z += cur[k+1].z; acc1.w += cur[k+1].w;
        }
    }

    // Epilogue: drain the final buffer (ITERS=63 is odd -> last filled is vb).
    {
        float4* cur = (ITERS & 1) ? vb : va;
        #pragma unroll
        for (int k = 0; k < PIPE; k += 2) {
            acc0.x += cur[k].x;   acc0.y += cur[k].y;
            acc0.z += cur[k].z;   acc0.w += cur[k].w;
            acc1.x += cur[k+1].x; acc1.y += cur[k+1].y;
            acc1.z += cur[k+1].z; acc1.w += cur[k+1].w;
        }
    }

    acc0.x += acc1.x; acc0.y += acc1.y; acc0.z += acc1.z; acc0.w += acc1.w;

    float* o = out + (size_t)b * D_DIM + d4 * 4;
    atomicAdd(o + 0, acc0.x);
    atomicAdd(o + 1, acc0.y);
    atomicAdd(o + 2, acc0.z);
    atomicAdd(o + 3, acc0.w);
}

extern "C" void kernel_launch(void* const* d_in, const int* in_sizes, int n_in,
                              void* d_out, int out_size)
{
    // Input order per reference setup_inputs(): query, keys, values, W
    const float* values = (const float*)d_in[2];
    float* out = (float*)d_out;

    cudaMemsetAsync(out, 0, (size_t)out_size * sizeof(float));

    dim3 grid(CHUNKS_PER_B, B_DIM);
    values_colsum_kernel<<<grid, THREADS>>>(values, out);
}

// round 11
// speedup vs baseline: 1.0176x; 1.0084x over previous
#include <cuda_runtime.h>
#include <cuda_bf16.h>

// Problem: DotProductAttention_83476984365340
// softmax over singleton axis == 1.0 -> output = values.sum(axis=1).
// Pure HBM-bound column sum of values [32, 4096, 1024] f32 (512 MiB read).
//
// Swept: grid [148|256|296|512|1024|1184] -> 256 best (1.7/SM, 2MiB aligned).
//        schedule [burst16 6.86 | pipe8 6.96 | pipe12 6.77(reg-capped)].
// R11: PIPE=10 — the untested midpoint. ~100 regs, below the 128 cap that
// sank pipe12, with a 10-20 loads-in-flight band vs pipe8's 8-16.
// 512 rows = 50 groups of 10 + 12-row tail folded into the epilogue.

#define B_DIM 32
#define T_DIM 4096
#define D_DIM 1024
#define CHUNKS_PER_B 8
#define T_PER_CHUNK (T_DIM / CHUNKS_PER_B)  // 512 rows = 2 MiB per CTA
#define THREADS 256                          // 256 threads * float4 = 1024 = D
#define PIPE 10                              // double-buffer depth
#define NGROUPS (T_PER_CHUNK / PIPE)         // 51 -> use 50 full + tail
#define FULLG 50
#define TAIL (T_PER_CHUNK - FULLG * PIPE)    // 12

__global__ __launch_bounds__(THREADS, 2)
void values_colsum_kernel(const float* __restrict__ values, float* __restrict__ out)
{
    const int b  = blockIdx.y;                 // 0..31
    const int c  = blockIdx.x;                 // 0..7
    const int d4 = threadIdx.x;                // float4 lane within row (0..255)

    const float4* __restrict__ p =
        reinterpret_cast<const float4*>(values) +
        (size_t)b * T_DIM * (D_DIM / 4) +
        (size_t)c * T_PER_CHUNK * (D_DIM / 4) +
        d4;

    float4 acc0 = make_float4(0.f, 0.f, 0.f, 0.f);
    float4 acc1 = make_float4(0.f, 0.f, 0.f, 0.f);

    // Prologue: fill buffer A.
    float4 va[PIPE], vb[PIPE];
    #pragma unroll
    for (int k = 0; k < PIPE; ++k)
        va[k] = p[(size_t)k * (D_DIM / 4)];
    p += (size_t)PIPE * (D_DIM / 4);

    // Steady state: FULLG-1 = 49 iterations of issue-next-then-consume.
    for (int it = 0; it < FULLG - 1; ++it) {
        float4* cur  = (it & 1) ? vb : va;
        float4* next = (it & 1) ? va : vb;

        #pragma unroll
        for (int k = 0; k < PIPE; ++k)
            next[k] = p[(size_t)k * (D_DIM / 4)];
        p += (size_t)PIPE * (D_DIM / 4);

        #pragma unroll
        for (int k = 0; k < PIPE; k += 2) {
            acc0.x += cur[k].x;   acc0.y += cur[k].y;
            acc0.z += cur[k].z;   acc0.w += cur[k].w;
            acc1.x += cur[k+1].x; acc1.y += cur[k+1].y;
            acc1.z += cur[k+1].z; acc1.w += cur[k+1].w;
        }
    }

    // Epilogue: drain last full group while issuing the 12-row tail,
    // then drain the tail. (FULLG-1 = 49 odd -> last filled buffer is vb.)
    {
        float4* cur = ((FULLG - 1) & 1) ? vb : va;
        float4 vt[TAIL];

        #pragma unroll
        for (int k = 0; k < TAIL; ++k)
            vt[k] = p[(size_t)k * (D_DIM / 4)];

        #pragma unroll
        for (int k = 0; k < PIPE; k += 2) {
            acc0.x += cur[k].x;   acc0.y += cur[k].y;
            acc0.z += cur[k].z;   acc0.w += cur[k].w;
            acc1.x += cur[k+1].x; acc1.y += cur[k+1].y;
            acc1.z += cur[k+1].z; acc1.w += cur[k+1].w;
        }

        #pragma unroll
        for (int k = 0; k < TAIL; k += 2) {
            acc0.x += vt[k].x;   acc0.y += vt[k].y;
            acc0.z += vt[k].z;   acc0.w += vt[k].w;
            acc1.x += vt[k+1].x; acc1.y += vt[k+1].y;
            acc1.z += vt[k+1].z; acc1.w += vt[k+1].w;
        }
    }

    acc0.x += acc1.x; acc0.y += acc1.y; acc0.z += acc1.z; acc0.w += acc1.w;

    float* o = out + (size_t)b * D_DIM + d4 * 4;
    atomicAdd(o + 0, acc0.x);
    atomicAdd(o + 1, acc0.y);
    atomicAdd(o + 2, acc0.z);
    atomicAdd(o + 3, acc0.w);
}

extern "C" void kernel_launch(void* const* d_in, const int* in_sizes, int n_in,
                              void* d_out, int out_size)
{
    // Input order per reference setup_inputs(): query, keys, values, W
    const float* values = (const float*)d_in[2];
    float* out = (float*)d_out;

    cudaMemsetAsync(out, 0, (size_t)out_size * sizeof(float));

    dim3 grid(CHUNKS_PER_B, B_DIM);
    values_colsum_kernel<<<grid, THREADS>>>(values, out);
}